// round 1
// baseline (speedup 1.0000x reference)
#include <cuda_runtime.h>
#include <cuda_bf16.h>
#include <stdint.h>

#define NMAX 50000
#define DIM  64

// ---------------- scratch (static device globals; no allocation) -------------
__device__ float g_ht[(size_t)NMAX * DIM];   // tangent features per node
__device__ float g_agg[(size_t)NMAX * DIM];  // segment sums
__device__ float g_deg[NMAX];                // degree sums
__device__ float g_h1[(size_t)NMAX * DIM];   // layer-1 output points
__device__ int   g_is64;                     // edges dtype flag

// ---------------- helpers ----------------------------------------------------
__device__ __forceinline__ float wsum(float v) {
#pragma unroll
    for (int o = 16; o; o >>= 1) v += __shfl_xor_sync(0xffffffffu, v, o);
    return v;
}
__device__ __forceinline__ float artanh_c(float x) {
    x = fminf(fmaxf(x, -1.0f + 1e-5f), 1.0f - 1e-5f);
    return atanhf(x);
}
__device__ __forceinline__ float tanh_c(float x) {
    return tanhf(fminf(fmaxf(x, -15.0f), 15.0f));
}

// ---------------- edges dtype detection -------------------------------------
// If the buffer is int32, reading it as int64 packs two random indices into
// one value -> almost surely out of [0, N). Only reads within the first E
// "int64 slots" = 8E bytes, which is safe for both layouts (int32 buffer is
// 8E bytes for 2E elements).
__global__ void detect_kernel(const long long* __restrict__ e64, int E, int N) {
    if (blockIdx.x != 0 || threadIdx.x != 0) return;
    int ok = 1;
    int cnt = E < 64 ? E : 64;
    for (int i = 0; i < cnt; i++) {
        long long v = e64[i];
        if (v < 0 || v >= (long long)N) { ok = 0; break; }
    }
    g_is64 = ok;
}

// ---------------- layer kernel 1: HypLinear + logmap0 ------------------------
// warp-per-4-nodes; 2 dims per lane (lane, lane+32).
__global__ void transform_kernel(const float* __restrict__ x,
                                 const float* __restrict__ W,
                                 const float* __restrict__ b,
                                 int n)
{
    __shared__ float sW[64 * 65];      // transposed, padded: sW[k*65 + j] = W[j][k]
    __shared__ float sbias[64];
    __shared__ float sy2;
    __shared__ float sx[8][4][64];

    const int tid = threadIdx.x, warp = tid >> 5, lane = tid & 31;

    for (int i = tid; i < 4096; i += 256) {
        int j = i >> 6, k = i & 63;
        sW[k * 65 + j] = W[i];
    }
    if (warp == 0) {
        // hyp_bias = proj(expmap0(b))
        float b0 = b[lane], b1 = b[lane + 32];
        float bn = fmaxf(sqrtf(wsum(b0 * b0 + b1 * b1)), 1e-7f);
        float t  = tanh_c(bn);
        float p0 = t * b0 / bn, p1 = t * b1 / bn;
        float pn2 = wsum(p0 * p0 + p1 * p1);
        float pn  = fmaxf(sqrtf(pn2), 1e-7f);
        if (pn > 1.0f - 1e-5f) { float s = (1.0f - 1e-5f) / pn; p0 *= s; p1 *= s; pn2 *= s * s; }
        sbias[lane] = p0; sbias[lane + 32] = p1;
        if (lane == 0) sy2 = pn2;
    }
    __syncthreads();

    int base = (blockIdx.x * 8 + warp) * 4;
    if (base >= n) return;

    float x0[4], x1[4], a0[4], a1[4];
#pragma unroll
    for (int r = 0; r < 4; r++) {
        int node = base + r;
        float v0 = 0.f, v1 = 0.f;
        if (node < n) {
            v0 = x[(size_t)node * 64 + lane];
            v1 = x[(size_t)node * 64 + 32 + lane];
        }
        x0[r] = v0; x1[r] = v1; a0[r] = 0.f; a1[r] = 0.f;
        sx[warp][r][lane] = v0; sx[warp][r][lane + 32] = v1;
    }
    __syncwarp();

#pragma unroll
    for (int k = 0; k < 64; k++) {
        float w0 = sW[k * 65 + lane];
        float w1 = sW[k * 65 + lane + 32];
#pragma unroll
        for (int r = 0; r < 4; r++) {
            float xk = sx[warp][r][k];
            a0[r] = fmaf(xk, w0, a0[r]);
            a1[r] = fmaf(xk, w1, a1[r]);
        }
    }

    float y2 = sy2;
    float p0 = sbias[lane], p1 = sbias[lane + 32];

#pragma unroll
    for (int r = 0; r < 4; r++) {
        int node = base + r;
        if (node >= n) break;   // uniform across the warp
        // mobius_matvec
        float xn  = fmaxf(sqrtf(wsum(x0[r] * x0[r] + x1[r] * x1[r])), 1e-7f);
        float mxn = fmaxf(sqrtf(wsum(a0[r] * a0[r] + a1[r] * a1[r])), 1e-7f);
        float t   = tanh_c(mxn / xn * artanh_c(xn));
        float h0 = t * a0[r] / mxn, h1 = t * a1[r] / mxn;
        // proj
        float hn2 = wsum(h0 * h0 + h1 * h1);
        float hn  = fmaxf(sqrtf(hn2), 1e-7f);
        if (hn > 1.0f - 1e-5f) { float s = (1.0f - 1e-5f) / hn; h0 *= s; h1 *= s; hn2 *= s * s; }
        // mobius_add(h, bias)
        float xy  = wsum(h0 * p0 + h1 * p1);
        float cA  = 1.0f + 2.0f * xy + y2;
        float cB  = 1.0f - hn2;
        float den = fmaxf(1.0f + 2.0f * xy + hn2 * y2, 1e-7f);
        float q0 = (cA * h0 + cB * p0) / den;
        float q1 = (cA * h1 + cB * p1) / den;
        // proj
        float qn = fmaxf(sqrtf(wsum(q0 * q0 + q1 * q1)), 1e-7f);
        if (qn > 1.0f - 1e-5f) { float s = (1.0f - 1e-5f) / qn; q0 *= s; q1 *= s; qn = 1.0f - 1e-5f; }
        // logmap0
        float l = artanh_c(qn) / qn;
        g_ht[(size_t)node * 64 + lane]      = l * q0;
        g_ht[(size_t)node * 64 + 32 + lane] = l * q1;
    }
}

// ---------------- layer kernel 2: zero accumulators --------------------------
__global__ void zero_kernel(int n) {
    int i = blockIdx.x * blockDim.x + threadIdx.x;
    int total = n * 64;
    if (i < total) g_agg[i] = 0.f;
    if (i < n)     g_deg[i] = 0.f;
}

// ---------------- layer kernel 3: edge scatter (segment_sum) -----------------
__global__ void scatter_kernel(const void* __restrict__ edges_raw,
                               const float* __restrict__ em, int E)
{
    int gw   = (int)(((size_t)blockIdx.x * blockDim.x + threadIdx.x) >> 5);
    int lane = threadIdx.x & 31;
    if (gw >= E) return;

    long long r, c;
    if (g_is64) {
        const long long* e = (const long long*)edges_raw;
        r = __ldg(&e[gw]);
        c = __ldg(&e[(size_t)E + gw]);
    } else {
        const int* e = (const int*)edges_raw;
        r = __ldg(&e[gw]);
        c = __ldg(&e[(size_t)E + gw]);
    }
    float m = __ldg(&em[gw]);

    const float* src = g_ht  + (size_t)c * 64;
    float*       dst = g_agg + (size_t)r * 64;
    atomicAdd(dst + lane,      __ldg(src + lane)      * m);
    atomicAdd(dst + 32 + lane, __ldg(src + 32 + lane) * m);
    if (lane == 0) atomicAdd(&g_deg[r], m);
}

// ---------------- layer kernel 4: HypAgg finish + HypAct ---------------------
__global__ void finalize_kernel(const float* __restrict__ node_mask,
                                float* __restrict__ out, int n)
{
    int warp = threadIdx.x >> 5, lane = threadIdx.x & 31;
    int node = blockIdx.x * 8 + warp;
    if (node >= n) return;

    float d  = fmaxf(g_deg[node], 1.0f);
    float a0 = g_agg[(size_t)node * 64 + lane]      / d;
    float a1 = g_agg[(size_t)node * 64 + 32 + lane] / d;

    // h = proj(expmap0(agg))
    float an = fmaxf(sqrtf(wsum(a0 * a0 + a1 * a1)), 1e-7f);
    float t  = tanh_c(an);
    float h0 = t * a0 / an, h1 = t * a1 / an;
    float hn = fmaxf(sqrtf(wsum(h0 * h0 + h1 * h1)), 1e-7f);
    if (hn > 1.0f - 1e-5f) { float s = (1.0f - 1e-5f) / hn; h0 *= s; h1 *= s; hn = 1.0f - 1e-5f; }

    // xt = relu(logmap0(h))
    float l  = artanh_c(hn) / hn;
    float u0 = fmaxf(l * h0, 0.f), u1 = fmaxf(l * h1, 0.f);

    // h = proj(expmap0(xt))
    float un = fmaxf(sqrtf(wsum(u0 * u0 + u1 * u1)), 1e-7f);
    float t2 = tanh_c(un);
    float o0 = t2 * u0 / un, o1 = t2 * u1 / un;
    float on = fmaxf(sqrtf(wsum(o0 * o0 + o1 * o1)), 1e-7f);
    if (on > 1.0f - 1e-5f) { float s = (1.0f - 1e-5f) / on; o0 *= s; o1 *= s; }

    float nm = node_mask[node];
    out[(size_t)node * 64 + lane]      = o0 * nm;
    out[(size_t)node * 64 + 32 + lane] = o1 * nm;
}

// ---------------- launch -----------------------------------------------------
extern "C" void kernel_launch(void* const* d_in, const int* in_sizes, int n_in,
                              void* d_out, int out_size)
{
    const float* h         = (const float*)d_in[0];
    // d_in[1] = distances (unused by the reference)
    const void*  edges     = d_in[2];
    const float* node_mask = (const float*)d_in[3];
    const float* edge_mask = (const float*)d_in[4];
    const float* W0        = (const float*)d_in[5];
    const float* b0        = (const float*)d_in[6];
    const float* W1        = (const float*)d_in[7];
    const float* b1        = (const float*)d_in[8];
    float*       out       = (float*)d_out;

    int N = in_sizes[0] / 64;
    int E = in_sizes[4];

    void* h1p = nullptr;
    cudaGetSymbolAddress(&h1p, g_h1);
    float* h1 = (float*)h1p;

    int tgrid = (N + 31) / 32;      // transform: 32 nodes / block
    int fgrid = (N + 7) / 8;        // finalize:  8 nodes / block
    int zgrid = (N * 64 + 255) / 256;
    int sgrid = (E + 7) / 8;        // scatter:   8 edges / block (warp-per-edge)

    detect_kernel<<<1, 32>>>((const long long*)edges, E, N);

    // ---- layer 1 ----
    transform_kernel<<<tgrid, 256>>>(h, W0, b0, N);
    zero_kernel<<<zgrid, 256>>>(N);
    scatter_kernel<<<sgrid, 256>>>(edges, edge_mask, E);
    finalize_kernel<<<fgrid, 256>>>(node_mask, h1, N);

    // ---- layer 2 ----
    transform_kernel<<<tgrid, 256>>>(h1, W1, b1, N);
    zero_kernel<<<zgrid, 256>>>(N);
    scatter_kernel<<<sgrid, 256>>>(edges, edge_mask, E);
    finalize_kernel<<<fgrid, 256>>>(node_mask, out, N);
}

// round 2
// speedup vs baseline: 1.3064x; 1.3064x over previous
#include <cuda_runtime.h>
#include <cuda_bf16.h>
#include <stdint.h>

#define NMAX 50000
#define DIM  64

// ---------------- scratch (static device globals; no allocation) -------------
__device__ __align__(128) float g_ht[(size_t)NMAX * DIM];   // tangent features
__device__ __align__(128) float g_agg[(size_t)NMAX * DIM];  // segment sums
__device__ __align__(128) float g_h1[(size_t)NMAX * DIM];   // layer-1 output
__device__ float g_deg[NMAX];                               // degree sums
__device__ int   g_is64;                                    // edges dtype flag

// ---------------- helpers ----------------------------------------------------
__device__ __forceinline__ float wsum(float v) {
#pragma unroll
    for (int o = 16; o; o >>= 1) v += __shfl_xor_sync(0xffffffffu, v, o);
    return v;
}
__device__ __forceinline__ float artanh_c(float x) {
    x = fminf(fmaxf(x, -1.0f + 1e-5f), 1.0f - 1e-5f);
    return atanhf(x);
}
__device__ __forceinline__ float tanh_c(float x) {
    return tanhf(fminf(fmaxf(x, -15.0f), 15.0f));
}
// Vectorized no-return reduction: 4 floats per op (sm_90+).
__device__ __forceinline__ void red_add_v4(float* addr, float a, float b, float c, float d) {
    asm volatile("red.global.add.v4.f32 [%0], {%1, %2, %3, %4};"
                 :: "l"(addr), "f"(a), "f"(b), "f"(c), "f"(d) : "memory");
}

// ---------------- edges dtype detection -------------------------------------
__global__ void detect_kernel(const long long* __restrict__ e64, int E, int N) {
    if (blockIdx.x != 0 || threadIdx.x != 0) return;
    int ok = 1;
    int cnt = E < 64 ? E : 64;
    for (int i = 0; i < cnt; i++) {
        long long v = e64[i];
        if (v < 0 || v >= (long long)N) { ok = 0; break; }
    }
    g_is64 = ok;
}

// ---------------- layer kernel 1: HypLinear + logmap0 ------------------------
__global__ void transform_kernel(const float* __restrict__ x,
                                 const float* __restrict__ W,
                                 const float* __restrict__ b,
                                 int n)
{
    __shared__ float sW[64 * 65];
    __shared__ float sbias[64];
    __shared__ float sy2;
    __shared__ float sx[8][4][64];

    const int tid = threadIdx.x, warp = tid >> 5, lane = tid & 31;

    for (int i = tid; i < 4096; i += 256) {
        int j = i >> 6, k = i & 63;
        sW[k * 65 + j] = W[i];
    }
    if (warp == 0) {
        float b0 = b[lane], b1 = b[lane + 32];
        float bn = fmaxf(sqrtf(wsum(b0 * b0 + b1 * b1)), 1e-7f);
        float t  = tanh_c(bn);
        float p0 = t * b0 / bn, p1 = t * b1 / bn;
        float pn2 = wsum(p0 * p0 + p1 * p1);
        float pn  = fmaxf(sqrtf(pn2), 1e-7f);
        if (pn > 1.0f - 1e-5f) { float s = (1.0f - 1e-5f) / pn; p0 *= s; p1 *= s; pn2 *= s * s; }
        sbias[lane] = p0; sbias[lane + 32] = p1;
        if (lane == 0) sy2 = pn2;
    }
    __syncthreads();

    int base = (blockIdx.x * 8 + warp) * 4;
    if (base >= n) return;

    float x0[4], x1[4], a0[4], a1[4];
#pragma unroll
    for (int r = 0; r < 4; r++) {
        int node = base + r;
        float v0 = 0.f, v1 = 0.f;
        if (node < n) {
            v0 = x[(size_t)node * 64 + lane];
            v1 = x[(size_t)node * 64 + 32 + lane];
        }
        x0[r] = v0; x1[r] = v1; a0[r] = 0.f; a1[r] = 0.f;
        sx[warp][r][lane] = v0; sx[warp][r][lane + 32] = v1;
    }
    __syncwarp();

#pragma unroll
    for (int k = 0; k < 64; k++) {
        float w0 = sW[k * 65 + lane];
        float w1 = sW[k * 65 + lane + 32];
#pragma unroll
        for (int r = 0; r < 4; r++) {
            float xk = sx[warp][r][k];
            a0[r] = fmaf(xk, w0, a0[r]);
            a1[r] = fmaf(xk, w1, a1[r]);
        }
    }

    float y2 = sy2;
    float p0 = sbias[lane], p1 = sbias[lane + 32];

#pragma unroll
    for (int r = 0; r < 4; r++) {
        int node = base + r;
        if (node >= n) break;
        float xn  = fmaxf(sqrtf(wsum(x0[r] * x0[r] + x1[r] * x1[r])), 1e-7f);
        float mxn = fmaxf(sqrtf(wsum(a0[r] * a0[r] + a1[r] * a1[r])), 1e-7f);
        float t   = tanh_c(mxn / xn * artanh_c(xn));
        float h0 = t * a0[r] / mxn, h1 = t * a1[r] / mxn;
        float hn2 = wsum(h0 * h0 + h1 * h1);
        float hn  = fmaxf(sqrtf(hn2), 1e-7f);
        if (hn > 1.0f - 1e-5f) { float s = (1.0f - 1e-5f) / hn; h0 *= s; h1 *= s; hn2 *= s * s; }
        float xy  = wsum(h0 * p0 + h1 * p1);
        float cA  = 1.0f + 2.0f * xy + y2;
        float cB  = 1.0f - hn2;
        float den = fmaxf(1.0f + 2.0f * xy + hn2 * y2, 1e-7f);
        float q0 = (cA * h0 + cB * p0) / den;
        float q1 = (cA * h1 + cB * p1) / den;
        float qn = fmaxf(sqrtf(wsum(q0 * q0 + q1 * q1)), 1e-7f);
        if (qn > 1.0f - 1e-5f) { float s = (1.0f - 1e-5f) / qn; q0 *= s; q1 *= s; qn = 1.0f - 1e-5f; }
        float l = artanh_c(qn) / qn;
        g_ht[(size_t)node * 64 + lane]      = l * q0;
        g_ht[(size_t)node * 64 + 32 + lane] = l * q1;
    }
}

// ---------------- layer kernel 2: zero accumulators --------------------------
__global__ void zero_kernel(int n) {
    int i = blockIdx.x * blockDim.x + threadIdx.x;
    int total = n * 16;  // float4 granularity
    if (i < total) ((float4*)g_agg)[i] = make_float4(0.f, 0.f, 0.f, 0.f);
    if (i < n)     g_deg[i] = 0.f;
}

// ---------------- layer kernel 3: edge scatter (segment_sum) -----------------
// 16 lanes per edge; one float4 gather + one red.add.v4.f32 per lane.
__global__ void scatter_kernel(const void* __restrict__ edges_raw,
                               const float* __restrict__ em, int E)
{
    int tid  = blockIdx.x * blockDim.x + threadIdx.x;
    int eid  = tid >> 4;          // edge index
    int sub  = tid & 15;          // float4 slot within the 64-dim row
    if (eid >= E) return;

    long long r, c;
    if (g_is64) {
        const long long* e = (const long long*)edges_raw;
        r = __ldg(&e[eid]);
        c = __ldg(&e[(size_t)E + eid]);
    } else {
        const int* e = (const int*)edges_raw;
        r = __ldg(&e[eid]);
        c = __ldg(&e[(size_t)E + eid]);
    }
    float m = __ldg(&em[eid]);

    const float4* src = (const float4*)(g_ht + (size_t)c * 64) + sub;
    float*        dst = g_agg + (size_t)r * 64 + sub * 4;
    float4 v = __ldg(src);
    red_add_v4(dst, v.x * m, v.y * m, v.z * m, v.w * m);
    if (sub == 0) atomicAdd(&g_deg[r], m);
}

// ---------------- layer kernel 4: HypAgg finish + HypAct ---------------------
__global__ void finalize_kernel(const float* __restrict__ node_mask,
                                float* __restrict__ out, int n)
{
    int warp = threadIdx.x >> 5, lane = threadIdx.x & 31;
    int node = blockIdx.x * 8 + warp;
    if (node >= n) return;

    float d  = fmaxf(g_deg[node], 1.0f);
    float a0 = g_agg[(size_t)node * 64 + lane]      / d;
    float a1 = g_agg[(size_t)node * 64 + 32 + lane] / d;

    float an = fmaxf(sqrtf(wsum(a0 * a0 + a1 * a1)), 1e-7f);
    float t  = tanh_c(an);
    float h0 = t * a0 / an, h1 = t * a1 / an;
    float hn = fmaxf(sqrtf(wsum(h0 * h0 + h1 * h1)), 1e-7f);
    if (hn > 1.0f - 1e-5f) { float s = (1.0f - 1e-5f) / hn; h0 *= s; h1 *= s; hn = 1.0f - 1e-5f; }

    float l  = artanh_c(hn) / hn;
    float u0 = fmaxf(l * h0, 0.f), u1 = fmaxf(l * h1, 0.f);

    float un = fmaxf(sqrtf(wsum(u0 * u0 + u1 * u1)), 1e-7f);
    float t2 = tanh_c(un);
    float o0 = t2 * u0 / un, o1 = t2 * u1 / un;
    float on = fmaxf(sqrtf(wsum(o0 * o0 + o1 * o1)), 1e-7f);
    if (on > 1.0f - 1e-5f) { float s = (1.0f - 1e-5f) / on; o0 *= s; o1 *= s; }

    float nm = node_mask[node];
    out[(size_t)node * 64 + lane]      = o0 * nm;
    out[(size_t)node * 64 + 32 + lane] = o1 * nm;
}

// ---------------- launch -----------------------------------------------------
extern "C" void kernel_launch(void* const* d_in, const int* in_sizes, int n_in,
                              void* d_out, int out_size)
{
    const float* h         = (const float*)d_in[0];
    const void*  edges     = d_in[2];
    const float* node_mask = (const float*)d_in[3];
    const float* edge_mask = (const float*)d_in[4];
    const float* W0        = (const float*)d_in[5];
    const float* b0        = (const float*)d_in[6];
    const float* W1        = (const float*)d_in[7];
    const float* b1        = (const float*)d_in[8];
    float*       out       = (float*)d_out;

    int N = in_sizes[0] / 64;
    int E = in_sizes[4];

    void* h1p = nullptr;
    cudaGetSymbolAddress(&h1p, g_h1);
    float* h1 = (float*)h1p;

    int tgrid = (N + 31) / 32;           // transform: 32 nodes / block
    int fgrid = (N + 7) / 8;             // finalize:  8 nodes / block
    int zgrid = (N * 16 + 255) / 256;    // zero: float4 granularity
    int sgrid = (E * 16 + 255) / 256;    // scatter: 16 lanes / edge

    detect_kernel<<<1, 32>>>((const long long*)edges, E, N);

    // ---- layer 1 ----
    transform_kernel<<<tgrid, 256>>>(h, W0, b0, N);
    zero_kernel<<<zgrid, 256>>>(N);
    scatter_kernel<<<sgrid, 256>>>(edges, edge_mask, E);
    finalize_kernel<<<fgrid, 256>>>(node_mask, h1, N);

    // ---- layer 2 ----
    transform_kernel<<<tgrid, 256>>>(h1, W1, b1, N);
    zero_kernel<<<zgrid, 256>>>(N);
    scatter_kernel<<<sgrid, 256>>>(edges, edge_mask, E);
    finalize_kernel<<<fgrid, 256>>>(node_mask, out, N);
}